// round 16
// baseline (speedup 1.0000x reference)
#include <cuda_runtime.h>
#include <cuda_bf16.h>
#include <math.h>
#include <stdint.h>

#define CC 768
#define NBLK 8
#define DR 17
#define MODES 17408              /* 17*32*32, layout [d'][h][w] */
#define NLINES 1572864
#define NPLANES 26112            /* 1536*17 */
#define S1 0.0055242717280199026f /* 1/sqrt(32768) */
#define LAMBDA 0.01f
#define KP 200                   /* padded bf16 K-stride in smem */

__device__ uint32_t g_Xb[26738688];          /* forward spectrum, bf16x2 */
__device__ __nv_bfloat16 g_Ybr[26738688];    /* MLP output, planar re bf16 */
__device__ __nv_bfloat16 g_Ybi[26738688];    /* MLP output, planar im bf16 */
__device__ __nv_bfloat16 g_Wexp[294912];     /* 8 blocks x 2 mats x 96x192 compact */

__constant__ float TWC[16] = {
  1.0f, 0.9807852804032304f, 0.9238795325112867f, 0.8314696123025452f,
  0.7071067811865476f, 0.5555702330196022f, 0.3826834323650898f, 0.19509032201612827f,
  0.0f, -0.19509032201612827f, -0.3826834323650898f, -0.5555702330196022f,
  -0.7071067811865476f, -0.8314696123025452f, -0.9238795325112867f, -0.9807852804032304f
};
__constant__ float TWS[16] = {
  0.0f, 0.19509032201612827f, 0.3826834323650898f, 0.5555702330196022f,
  0.7071067811865476f, 0.8314696123025452f, 0.9238795325112867f, 0.9807852804032304f,
  1.0f, 0.9807852804032304f, 0.9238795325112867f, 0.8314696123025452f,
  0.7071067811865476f, 0.5555702330196022f, 0.3826834323650898f, 0.19509032201612827f
};

template<bool INV>
__device__ __forceinline__ void fft32(float2* v) {
  constexpr int br[32] = {0,16,8,24,4,20,12,28,2,18,10,26,6,22,14,30,
                          1,17,9,25,5,21,13,29,3,19,11,27,7,23,15,31};
  #pragma unroll
  for (int i = 0; i < 32; i++) {
    int j = br[i];
    if (j > i) { float2 tmp = v[i]; v[i] = v[j]; v[j] = tmp; }
  }
  #pragma unroll
  for (int s = 1; s <= 5; s++) {
    const int m = 1 << s, hm = m >> 1;
    #pragma unroll
    for (int j = 0; j < hm; j++) {
      const int ti = j << (5 - s);
      const float wr = TWC[ti];
      const float wi = INV ? TWS[ti] : -TWS[ti];
      #pragma unroll
      for (int k = j; k < 32; k += m) {
        float2 a = v[k], b = v[k + hm];
        float tr = fmaf(b.x, wr, -b.y * wi);
        float tq = fmaf(b.x, wi,  b.y * wr);
        v[k]      = make_float2(a.x + tr, a.y + tq);
        v[k + hm] = make_float2(a.x - tr, a.y - tq);
      }
    }
  }
}

__device__ __forceinline__ uint32_t packbf(float2 a) {
  __nv_bfloat162 pk = __float22bfloat162_rn(a);
  return *(uint32_t*)&pk;
}
__device__ __forceinline__ float2 unpackbf(uint32_t u) {
  return __bfloat1622float2(*(__nv_bfloat162*)&u);
}

// ---------------- Pass 1: rFFT along D, one line per thread, no smem ----------------
// First 8 CTAs additionally expand weights into compact bf16 [Wr | -Wi] form.
__global__ void __launch_bounds__(256) k_rfft_d(const float* __restrict__ x,
    const float* __restrict__ w1r, const float* __restrict__ w1i,
    const float* __restrict__ w2r, const float* __restrict__ w2i) {
  const int t = threadIdx.x;
  const int line = blockIdx.x * 256 + t;
  const int lane = line & 31;
  float2 v[32];
  const float4* src = (const float4*)(x + (long long)line * 32);
  #pragma unroll
  for (int q = 0; q < 8; q++) {
    const float4 u = src[q];
    v[q * 4]     = make_float2(u.x, 0.0f);
    v[q * 4 + 1] = make_float2(u.y, 0.0f);
    v[q * 4 + 2] = make_float2(u.z, 0.0f);
    v[q * 4 + 3] = make_float2(u.w, 0.0f);
  }
  fft32<false>(v);
  const int bc = line >> 10, h = (line >> 5) & 31;
  const long long ob = (long long)bc * MODES + h * 32 + lane;
  #pragma unroll
  for (int k = 0; k < DR; k++)
    g_Xb[ob + k * 1024] = packbf(make_float2(v[k].x * S1, v[k].y * S1));
  // folded weight prep (runs concurrently with the rest of the grid)
  if (blockIdx.x < NBLK) {
    const int nb = blockIdx.x;
    const int wb = nb * 9216;
    __nv_bfloat16* g1 = g_Wexp + nb * 36864;
    __nv_bfloat16* g2 = g1 + 18432;
    for (int idx = t; idx < 9216; idx += 256) {
      const int i = idx / 96, o = idx % 96;
      g1[o * 192 + i]      = __float2bfloat16_rn(w1r[wb + idx]);
      g1[o * 192 + i + 96] = __float2bfloat16_rn(-w1i[wb + idx]);
      g2[o * 192 + i]      = __float2bfloat16_rn(w2r[wb + idx]);
      g2[o * 192 + i + 96] = __float2bfloat16_rn(-w2i[wb + idx]);
    }
  }
}

// ---------------- Pass 2: forward W+H FFT, single smem transpose ----------------
__global__ void __launch_bounds__(256) k_fft_wh_fwd() {
  extern __shared__ uint32_t smu[];            // 8 planes x [32][33] bf16x2
  const int t = threadIdx.x, p = t >> 5, lane = t & 31;
  uint32_t* pl = smu + p * 1056;
  const long long pb = (long long)(blockIdx.x * 8 + p) * 1024;
  uint32_t row[32];
  const uint4* gsrc = (const uint4*)(g_Xb + pb + lane * 32);
  #pragma unroll
  for (int q = 0; q < 8; q++) {
    const uint4 u = gsrc[q];
    row[q * 4] = u.x; row[q * 4 + 1] = u.y; row[q * 4 + 2] = u.z; row[q * 4 + 3] = u.w;
  }
  float2 v[32];
  #pragma unroll
  for (int w = 0; w < 32; w++) v[w] = unpackbf(row[w]);
  fft32<false>(v);
  #pragma unroll
  for (int w = 0; w < 32; w++) pl[lane * 33 + w] = packbf(v[w]);
  __syncwarp();
  #pragma unroll
  for (int h = 0; h < 32; h++) v[h] = unpackbf(pl[h * 33 + lane]);
  fft32<false>(v);
  #pragma unroll
  for (int h = 0; h < 32; h++) g_Xb[pb + h * 32 + lane] = packbf(v[h]);
}

// ---------------- Pass 4: inverse W+H FFT, single smem transpose ----------------
__global__ void __launch_bounds__(256) k_fft_wh_inv() {
  extern __shared__ uint32_t smu[];
  const int t = threadIdx.x, p = t >> 5, lane = t & 31;
  uint32_t* pl = smu + p * 1056;
  const long long pb = (long long)(blockIdx.x * 8 + p) * 1024;
  uint32_t rbuf[16], ibuf[16];
  const uint4* rsrc = (const uint4*)(g_Ybr + pb + lane * 32);
  const uint4* isrc = (const uint4*)(g_Ybi + pb + lane * 32);
  #pragma unroll
  for (int q = 0; q < 4; q++) {
    const uint4 a = rsrc[q];
    rbuf[q * 4] = a.x; rbuf[q * 4 + 1] = a.y; rbuf[q * 4 + 2] = a.z; rbuf[q * 4 + 3] = a.w;
    const uint4 b = isrc[q];
    ibuf[q * 4] = b.x; ibuf[q * 4 + 1] = b.y; ibuf[q * 4 + 2] = b.z; ibuf[q * 4 + 3] = b.w;
  }
  float2 v[32];
  #pragma unroll
  for (int j = 0; j < 16; j++) {
    const uint32_t r2 = rbuf[j], i2 = ibuf[j];
    v[2 * j]     = unpackbf((r2 & 0x0000ffffu) | (i2 << 16));
    v[2 * j + 1] = unpackbf((r2 >> 16) | (i2 & 0xffff0000u));
  }
  fft32<true>(v);
  #pragma unroll
  for (int w = 0; w < 32; w++) pl[lane * 33 + w] = packbf(v[w]);
  __syncwarp();
  #pragma unroll
  for (int h = 0; h < 32; h++) v[h] = unpackbf(pl[h * 33 + lane]);
  fft32<true>(v);
  #pragma unroll
  for (int h = 0; h < 32; h++) {
    const uint32_t u = packbf(v[h]);
    g_Ybr[pb + h * 32 + lane] = *(__nv_bfloat16*)&u;
    const uint32_t hi = u >> 16;
    g_Ybi[pb + h * 32 + lane] = *(__nv_bfloat16*)&hi;
  }
}

// ---------------- Pass 3: HMMA MLP, 384 thr, 2 CTAs/SM, templated swap ----------------
__device__ __forceinline__ float geluf(float v) {
  return 0.5f * v * (1.0f + erff(v * 0.7071067811865476f));
}
__device__ __forceinline__ float sshrink(float v) {
  float a = fabsf(v) - LAMBDA;
  return a > 0.0f ? copysignf(a, v) : 0.0f;
}
__device__ __forceinline__ uint32_t sptr(const void* p) {
  return (uint32_t)__cvta_generic_to_shared(p);
}
__device__ __forceinline__ void ldm4(uint32_t a, uint32_t r[4]) {
  asm volatile("ldmatrix.sync.aligned.m8n8.x4.shared.b16 {%0,%1,%2,%3},[%4];\n"
               : "=r"(r[0]), "=r"(r[1]), "=r"(r[2]), "=r"(r[3]) : "r"(a));
}
__device__ __forceinline__ void mma16816(float* d, const uint32_t* a,
                                         uint32_t b0, uint32_t b1) {
  asm volatile(
    "mma.sync.aligned.m16n8k16.row.col.f32.bf16.bf16.f32 "
    "{%0,%1,%2,%3},{%4,%5,%6,%7},{%8,%9},{%0,%1,%2,%3};\n"
    : "+f"(d[0]), "+f"(d[1]), "+f"(d[2]), "+f"(d[3])
    : "r"(a[0]), "r"(a[1]), "r"(a[2]), "r"(a[3]), "r"(b0), "r"(b1));
}
// Fragments for logical K-step ks; weights stored compact [Wr | -Wi] (96 rows).
// SWAP warps (out cols 96..191) read stored step (ks+6)%12; for ks<6 the
// fragment is negated via sign-bit XOR:  [Wi | Wr] = (half-swap, flip) of [Wr | -Wi].
template<bool SWAP>
__device__ __forceinline__ void loadfr(const uint16_t* As, const uint16_t* Ws,
                                       int arow0, int arow1, int wrow, int ks,
                                       int lcolh, uint32_t a[2][4], uint32_t w[2][4]) {
  ldm4(sptr(As + arow0 * KP + ks * 16 + lcolh), a[0]);
  ldm4(sptr(As + arow1 * KP + ks * 16 + lcolh), a[1]);
  const int sks = SWAP ? (ks < 6 ? ks + 6 : ks - 6) : ks;
  #pragma unroll
  for (int p = 0; p < 2; p++) {
    ldm4(sptr(Ws + (wrow + p * 16) * KP + sks * 16 + lcolh), w[p]);
    if (SWAP && ks < 6) {
      #pragma unroll
      for (int e = 0; e < 4; e++) w[p][e] ^= 0x80008000u;
    }
  }
}
template<bool SWAP>
__device__ __forceinline__ void gemmPipe(const uint16_t* As, const uint16_t* Ws,
                                         int mwo, int nwo, int lrow, int lcolh,
                                         float acc[2][4][4]) {
  #pragma unroll
  for (int mt = 0; mt < 2; mt++)
    #pragma unroll
    for (int nt = 0; nt < 4; nt++)
      #pragma unroll
      for (int e = 0; e < 4; e++) acc[mt][nt][e] = 0.0f;
  const int arow0 = mwo + lrow, arow1 = mwo + 16 + lrow;
  const int wrow = (nwo % 96) + lrow;
  uint32_t a[2][2][4], w[2][2][4];
  loadfr<SWAP>(As, Ws, arow0, arow1, wrow, 0, lcolh, a[0], w[0]);
  #pragma unroll
  for (int ks = 0; ks < 12; ks++) {
    const int cur = ks & 1;
    if (ks < 11)
      loadfr<SWAP>(As, Ws, arow0, arow1, wrow, ks + 1, lcolh,
                   a[cur ^ 1], w[cur ^ 1]);
    #pragma unroll
    for (int p = 0; p < 2; p++)
      #pragma unroll
      for (int mt = 0; mt < 2; mt++) {
        mma16816(acc[mt][2 * p],     a[cur][mt], w[cur][p][0], w[cur][p][2]);
        mma16816(acc[mt][2 * p + 1], a[cur][mt], w[cur][p][1], w[cur][p][3]);
      }
  }
}

#define OFF_AS 0
#define OFF_W1 25600             /* As: 64*200*2 */
#define OFF_W2 64000             /* W1c: 96*200*2 */
#define OFF_B1 102400
#define OFF_B2 103168
#define SM_TOTAL 103936
#define NTHR 384
#define TILES_PER_CTA 8

__global__ void __launch_bounds__(NTHR, 2) k_cgemm(
    const float* __restrict__ b1r, const float* __restrict__ b1i,
    const float* __restrict__ b2r, const float* __restrict__ b2i) {
  extern __shared__ char smraw[];
  uint16_t* Asu = (uint16_t*)(smraw + OFF_AS);
  uint16_t* W1u = (uint16_t*)(smraw + OFF_W1);
  uint16_t* W2u = (uint16_t*)(smraw + OFF_W2);
  float* b1s = (float*)(smraw + OFF_B1);
  float* b2s = (float*)(smraw + OFF_B2);

  const int t = threadIdx.x, wid = t >> 5, lane = t & 31;
  const int b = blockIdx.y, nb = blockIdx.z;

  if (t < 192) {
    b1s[t] = (t < 96) ? b1r[nb * 96 + t] : b1i[nb * 96 + t - 96];
    b2s[t] = (t < 96) ? b2r[nb * 96 + t] : b2i[nb * 96 + t - 96];
  }
  // compact weights -> smem via uint4 (96 rows x 192 cols each)
  const __nv_bfloat16* gw = g_Wexp + nb * 36864;
  for (int idx = t; idx < 2304; idx += NTHR) {
    const int n = idx / 24, c8 = (idx % 24) * 8;
    *(uint4*)(W1u + n * KP + c8) = *(const uint4*)(gw + n * 192 + c8);
    *(uint4*)(W2u + n * KP + c8) = *(const uint4*)(gw + 18432 + n * 192 + c8);
  }

  const long long chbase = ((long long)b * CC + nb * 96) * MODES;
  const int mwo = (wid & 1) * 32, nwo = (wid >> 1) * 32;   // 2m x 6n warps
  const bool swap = (nwo >= 96);
  const int lrow = lane & 15, lcolh = (lane >> 4) * 8;
  const int frow = lane >> 2, fcol = 2 * (lane & 3);
  __nv_bfloat16* dstb = swap ? g_Ybi : g_Ybr;
  const int nh = nwo % 96;

  // A-fill decomposition: thread owns mode mm, channel group ig (16 channels)
  const int fmm = t & 63, fig = t >> 6;

  #pragma unroll 1
  for (int it = 0; it < TILES_PER_CTA; it++) {
    const int m0 = (blockIdx.x * TILES_PER_CTA + it) * 64;
    __syncthreads();   // weights ready (it=0) / previous GEMM2 reads done
    // A tile: 16 coalesced LDG -> register transpose -> 4 conflict-free STS.128
    {
      const long long gb = chbase + (long long)(fig * 16) * MODES + m0 + fmm;
      uint32_t u[16];
      #pragma unroll
      for (int j = 0; j < 16; j++) u[j] = g_Xb[gb + (long long)j * MODES];
      uint32_t re[8], im[8];
      #pragma unroll
      for (int j = 0; j < 8; j++) {
        re[j] = (u[2 * j] & 0x0000ffffu) | (u[2 * j + 1] << 16);
        im[j] = (u[2 * j] >> 16)         | (u[2 * j + 1] & 0xffff0000u);
      }
      uint4* pre = (uint4*)(Asu + fmm * KP + fig * 16);
      pre[0] = make_uint4(re[0], re[1], re[2], re[3]);
      pre[1] = make_uint4(re[4], re[5], re[6], re[7]);
      uint4* pim = (uint4*)(Asu + fmm * KP + 96 + fig * 16);
      pim[0] = make_uint4(im[0], im[1], im[2], im[3]);
      pim[1] = make_uint4(im[4], im[5], im[6], im[7]);
    }
    __syncthreads();

    float acc[2][4][4];
    if (swap) gemmPipe<true >(Asu, W1u, mwo, nwo, lrow, lcolh, acc);
    else      gemmPipe<false>(Asu, W1u, mwo, nwo, lrow, lcolh, acc);
    __syncthreads();   // all GEMM1 reads of As done

    #pragma unroll
    for (int mt = 0; mt < 2; mt++)
      #pragma unroll
      for (int nt = 0; nt < 4; nt++) {
        const int col = nwo + nt * 8 + fcol;
        const float bl = b1s[col], bh = b1s[col + 1];
        const int r0 = mwo + mt * 16 + frow;
        __nv_bfloat162 p0, p1;
        p0.x = __float2bfloat16_rn(geluf(acc[mt][nt][0] + bl));
        p0.y = __float2bfloat16_rn(geluf(acc[mt][nt][1] + bh));
        p1.x = __float2bfloat16_rn(geluf(acc[mt][nt][2] + bl));
        p1.y = __float2bfloat16_rn(geluf(acc[mt][nt][3] + bh));
        *(__nv_bfloat162*)(Asu + r0 * KP + col)       = p0;
        *(__nv_bfloat162*)(Asu + (r0 + 8) * KP + col) = p1;
      }
    __syncthreads();   // H1 visible

    if (swap) gemmPipe<true >(Asu, W2u, mwo, nwo, lrow, lcolh, acc);
    else      gemmPipe<false>(Asu, W2u, mwo, nwo, lrow, lcolh, acc);

    #pragma unroll
    for (int mt = 0; mt < 2; mt++)
      #pragma unroll
      for (int nt = 0; nt < 4; nt++) {
        const int c0 = nh + nt * 8 + fcol;
        const float bl = b2s[nwo + nt * 8 + fcol], bh = b2s[nwo + nt * 8 + fcol + 1];
        const int row = mwo + mt * 16 + frow;
        const long long base = chbase + (long long)c0 * MODES + m0 + row;
        dstb[base]             = __float2bfloat16_rn(sshrink(acc[mt][nt][0] + bl));
        dstb[base + MODES]     = __float2bfloat16_rn(sshrink(acc[mt][nt][1] + bh));
        dstb[base + 8]         = __float2bfloat16_rn(sshrink(acc[mt][nt][2] + bl));
        dstb[base + MODES + 8] = __float2bfloat16_rn(sshrink(acc[mt][nt][3] + bh));
      }
  }
}

// ---------------- Pass 5: inverse rFFT along D, one line per thread, no smem ----------------
__global__ void __launch_bounds__(256) k_irfft_d(const float* __restrict__ x,
                                                 float* __restrict__ out) {
  const int t = threadIdx.x;
  const int line = blockIdx.x * 256 + t;
  const int lane = line & 31;
  const int bc = line >> 10, h = (line >> 5) & 31;
  float2 v[32];
  const long long ib = (long long)bc * MODES + h * 32 + lane;
  #pragma unroll
  for (int k = 0; k < DR; k++)
    v[k] = make_float2(__bfloat162float(g_Ybr[ib + k * 1024]),
                       __bfloat162float(g_Ybi[ib + k * 1024]));
  #pragma unroll
  for (int k = DR; k < 32; k++) {
    const float2 z = v[32 - k];
    v[k] = make_float2(z.x, -z.y);
  }
  fft32<true>(v);
  const float4* src = (const float4*)(x + (long long)line * 32);
  float4* dst = (float4*)(out + (long long)line * 32);
  #pragma unroll
  for (int q = 0; q < 8; q++) {
    const float4 u = src[q];
    float4 o;
    o.x = fmaf(v[q * 4].x,     S1, u.x);
    o.y = fmaf(v[q * 4 + 1].x, S1, u.y);
    o.z = fmaf(v[q * 4 + 2].x, S1, u.z);
    o.w = fmaf(v[q * 4 + 3].x, S1, u.w);
    dst[q] = o;
  }
}

// ---------------- launch ----------------
extern "C" void kernel_launch(void* const* d_in, const int* in_sizes, int n_in,
                              void* d_out, int out_size) {
  const float* x   = (const float*)d_in[0];
  const float* w1r = (const float*)d_in[1];
  const float* w1i = (const float*)d_in[2];
  const float* w2r = (const float*)d_in[3];
  const float* w2i = (const float*)d_in[4];
  const float* b1r = (const float*)d_in[5];
  const float* b1i = (const float*)d_in[6];
  const float* b2r = (const float*)d_in[7];
  const float* b2i = (const float*)d_in[8];
  float* out = (float*)d_out;

  const int fftBytes = 8 * 1056 * (int)sizeof(uint32_t);   // 33792

  cudaFuncSetAttribute(k_fft_wh_fwd,
                       cudaFuncAttributeMaxDynamicSharedMemorySize, fftBytes);
  cudaFuncSetAttribute(k_fft_wh_inv,
                       cudaFuncAttributeMaxDynamicSharedMemorySize, fftBytes);
  cudaFuncSetAttribute(k_cgemm,
                       cudaFuncAttributeMaxDynamicSharedMemorySize, SM_TOTAL);

  k_rfft_d<<<NLINES / 256, 256>>>(x, w1r, w1i, w2r, w2i);
  k_fft_wh_fwd<<<NPLANES / 8, 256, fftBytes>>>();
  dim3 g3(MODES / (64 * TILES_PER_CTA), 2, NBLK);
  k_cgemm<<<g3, NTHR, SM_TOTAL>>>(b1r, b1i, b2r, b2i);
  k_fft_wh_inv<<<NPLANES / 8, 256, fftBytes>>>();
  k_irfft_d<<<NLINES / 256, 256>>>(x, out);
}

// round 17
// speedup vs baseline: 1.0944x; 1.0944x over previous
#include <cuda_runtime.h>
#include <cuda_bf16.h>
#include <math.h>
#include <stdint.h>

#define CC 768
#define NBLK 8
#define DR 17
#define MODES 17408              /* 17*32*32, layout [d'][h][w] */
#define NLINES 1572864
#define NPLANES 26112            /* 1536*17 */
#define S1 0.0055242717280199026f /* 1/sqrt(32768) */
#define LAMBDA 0.01f
#define KP 200                   /* padded bf16 K-stride in smem */

__device__ uint32_t g_Xb[26738688];          /* forward spectrum, bf16x2 */
__device__ uint32_t g_Yb[26738688];          /* MLP output, bf16x2 (re|im) */
__device__ __nv_bfloat16 g_Wexp[294912];     /* 8 blocks x 2 mats x 96x192 compact */

__constant__ float TWC[16] = {
  1.0f, 0.9807852804032304f, 0.9238795325112867f, 0.8314696123025452f,
  0.7071067811865476f, 0.5555702330196022f, 0.3826834323650898f, 0.19509032201612827f,
  0.0f, -0.19509032201612827f, -0.3826834323650898f, -0.5555702330196022f,
  -0.7071067811865476f, -0.8314696123025452f, -0.9238795325112867f, -0.9807852804032304f
};
__constant__ float TWS[16] = {
  0.0f, 0.19509032201612827f, 0.3826834323650898f, 0.5555702330196022f,
  0.7071067811865476f, 0.8314696123025452f, 0.9238795325112867f, 0.9807852804032304f,
  1.0f, 0.9807852804032304f, 0.9238795325112867f, 0.8314696123025452f,
  0.7071067811865476f, 0.5555702330196022f, 0.3826834323650898f, 0.19509032201612827f
};

template<bool INV>
__device__ __forceinline__ void fft32(float2* v) {
  constexpr int br[32] = {0,16,8,24,4,20,12,28,2,18,10,26,6,22,14,30,
                          1,17,9,25,5,21,13,29,3,19,11,27,7,23,15,31};
  #pragma unroll
  for (int i = 0; i < 32; i++) {
    int j = br[i];
    if (j > i) { float2 tmp = v[i]; v[i] = v[j]; v[j] = tmp; }
  }
  #pragma unroll
  for (int s = 1; s <= 5; s++) {
    const int m = 1 << s, hm = m >> 1;
    #pragma unroll
    for (int j = 0; j < hm; j++) {
      const int ti = j << (5 - s);
      const float wr = TWC[ti];
      const float wi = INV ? TWS[ti] : -TWS[ti];
      #pragma unroll
      for (int k = j; k < 32; k += m) {
        float2 a = v[k], b = v[k + hm];
        float tr = fmaf(b.x, wr, -b.y * wi);
        float tq = fmaf(b.x, wi,  b.y * wr);
        v[k]      = make_float2(a.x + tr, a.y + tq);
        v[k + hm] = make_float2(a.x - tr, a.y - tq);
      }
    }
  }
}

__device__ __forceinline__ uint32_t packbf(float2 a) {
  __nv_bfloat162 pk = __float22bfloat162_rn(a);
  return *(uint32_t*)&pk;
}
__device__ __forceinline__ float2 unpackbf(uint32_t u) {
  return __bfloat1622float2(*(__nv_bfloat162*)&u);
}

// ---------------- Pass 1: rFFT along D -> bf16 plane-major spectrum ----------------
__global__ void __launch_bounds__(256) k_rfft_d(const float* __restrict__ x,
    const float* __restrict__ w1r, const float* __restrict__ w1i,
    const float* __restrict__ w2r, const float* __restrict__ w2i) {
  __shared__ float sIn[8][32][33];
  const int t = threadIdx.x, warp = t >> 5, lane = t & 31;
  const int line0 = blockIdx.x * 256 + warp * 32;
  const float* src = x + (long long)line0 * 32;
  #pragma unroll
  for (int r = 0; r < 32; r++) sIn[warp][r][lane] = src[r * 32 + lane];
  __syncwarp();
  float2 v[32];
  #pragma unroll
  for (int d = 0; d < 32; d++) v[d] = make_float2(sIn[warp][lane][d], 0.0f);
  fft32<false>(v);
  const int bc = line0 >> 10, h = (line0 >> 5) & 31;
  const long long ob = (long long)bc * MODES + h * 32 + lane;
  #pragma unroll
  for (int k = 0; k < DR; k++)
    g_Xb[ob + k * 1024] = packbf(make_float2(v[k].x * S1, v[k].y * S1));
  if (blockIdx.x < NBLK) {
    const int nb = blockIdx.x;
    const int wb = nb * 9216;
    __nv_bfloat16* g1 = g_Wexp + nb * 36864;
    __nv_bfloat16* g2 = g1 + 18432;
    for (int idx = t; idx < 9216; idx += 256) {
      const int i = idx / 96, o = idx % 96;
      g1[o * 192 + i]      = __float2bfloat16_rn(w1r[wb + idx]);
      g1[o * 192 + i + 96] = __float2bfloat16_rn(-w1i[wb + idx]);
      g2[o * 192 + i]      = __float2bfloat16_rn(w2r[wb + idx]);
      g2[o * 192 + i + 96] = __float2bfloat16_rn(-w2i[wb + idx]);
    }
  }
}

// ---------------- Passes 2/4: W+H FFT, single smem transpose ----------------
template<bool INV, bool USEY>
__global__ void __launch_bounds__(256) k_fft_wh() {
  extern __shared__ uint32_t smu[];            // 8 planes x [32][33] bf16x2
  uint32_t* data = USEY ? g_Yb : g_Xb;
  const int t = threadIdx.x, p = t >> 5, lane = t & 31;
  uint32_t* pl = smu + p * 1056;
  const long long pb = (long long)(blockIdx.x * 8 + p) * 1024;
  uint32_t row[32];
  const uint4* gsrc = (const uint4*)(data + pb + lane * 32);
  #pragma unroll
  for (int q = 0; q < 8; q++) {
    const uint4 u = gsrc[q];
    row[q * 4] = u.x; row[q * 4 + 1] = u.y; row[q * 4 + 2] = u.z; row[q * 4 + 3] = u.w;
  }
  float2 v[32];
  #pragma unroll
  for (int w = 0; w < 32; w++) v[w] = unpackbf(row[w]);
  fft32<INV>(v);
  #pragma unroll
  for (int w = 0; w < 32; w++) pl[lane * 33 + w] = packbf(v[w]);
  __syncwarp();
  #pragma unroll
  for (int h = 0; h < 32; h++) v[h] = unpackbf(pl[h * 33 + lane]);
  fft32<INV>(v);
  #pragma unroll
  for (int h = 0; h < 32; h++) data[pb + h * 32 + lane] = packbf(v[h]);
}

// ---------------- Pass 3: HMMA MLP, 384 thr, 2 CTAs/SM, paired re/im warps ----------------
__device__ __forceinline__ float geluf(float v) {
  return 0.5f * v * (1.0f + erff(v * 0.7071067811865476f));
}
__device__ __forceinline__ float sshrink(float v) {
  float a = fabsf(v) - LAMBDA;
  return a > 0.0f ? copysignf(a, v) : 0.0f;
}
__device__ __forceinline__ uint32_t sptr(const void* p) {
  return (uint32_t)__cvta_generic_to_shared(p);
}
__device__ __forceinline__ void ldm4(uint32_t a, uint32_t r[4]) {
  asm volatile("ldmatrix.sync.aligned.m8n8.x4.shared.b16 {%0,%1,%2,%3},[%4];\n"
               : "=r"(r[0]), "=r"(r[1]), "=r"(r[2]), "=r"(r[3]) : "r"(a));
}
__device__ __forceinline__ void mma16816(float* d, const uint32_t* a,
                                         uint32_t b0, uint32_t b1) {
  asm volatile(
    "mma.sync.aligned.m16n8k16.row.col.f32.bf16.bf16.f32 "
    "{%0,%1,%2,%3},{%4,%5,%6,%7},{%8,%9},{%0,%1,%2,%3};\n"
    : "+f"(d[0]), "+f"(d[1]), "+f"(d[2]), "+f"(d[3])
    : "r"(a[0]), "r"(a[1]), "r"(a[2]), "r"(a[3]), "r"(b0), "r"(b1));
}
// Warp owns out cols [cb, cb+16) (re, frag p=0) and [96+cb, 96+cb+16) (im, p=1).
// Weights stored compact [Wr | -Wi] (96 rows). Fragment p=1 at logical K-step ks
// reads stored step (ks+6)%12 of the SAME stored rows; sign-flip XOR when ks<6.
__device__ __forceinline__ void loadfr(const uint16_t* As, const uint16_t* Ws,
                                       int arow0, int arow1, int wrow, int ks,
                                       int lcolh, uint32_t a[2][4], uint32_t w[2][4]) {
  ldm4(sptr(As + arow0 * KP + ks * 16 + lcolh), a[0]);
  ldm4(sptr(As + arow1 * KP + ks * 16 + lcolh), a[1]);
  ldm4(sptr(Ws + wrow * KP + ks * 16 + lcolh), w[0]);
  const int sks = (ks < 6) ? ks + 6 : ks - 6;
  ldm4(sptr(Ws + wrow * KP + sks * 16 + lcolh), w[1]);
  if (ks < 6) {
    #pragma unroll
    for (int e = 0; e < 4; e++) w[1][e] ^= 0x80008000u;
  }
}
__device__ __forceinline__ void gemmPipe(const uint16_t* As, const uint16_t* Ws,
                                         int mwo, int cb, int lrow, int lcolh,
                                         float acc[2][4][4]) {
  #pragma unroll
  for (int mt = 0; mt < 2; mt++)
    #pragma unroll
    for (int nt = 0; nt < 4; nt++)
      #pragma unroll
      for (int e = 0; e < 4; e++) acc[mt][nt][e] = 0.0f;
  const int arow0 = mwo + lrow, arow1 = mwo + 16 + lrow;
  const int wrow = cb + lrow;
  uint32_t a[2][2][4], w[2][2][4];
  loadfr(As, Ws, arow0, arow1, wrow, 0, lcolh, a[0], w[0]);
  #pragma unroll
  for (int ks = 0; ks < 12; ks++) {
    const int cur = ks & 1;
    if (ks < 11)
      loadfr(As, Ws, arow0, arow1, wrow, ks + 1, lcolh, a[cur ^ 1], w[cur ^ 1]);
    #pragma unroll
    for (int p = 0; p < 2; p++)
      #pragma unroll
      for (int mt = 0; mt < 2; mt++) {
        mma16816(acc[mt][2 * p],     a[cur][mt], w[cur][p][0], w[cur][p][2]);
        mma16816(acc[mt][2 * p + 1], a[cur][mt], w[cur][p][1], w[cur][p][3]);
      }
  }
}

#define OFF_AS 0
#define OFF_W1 25600             /* As: 64*200*2 */
#define OFF_W2 64000             /* W1c: 96*200*2 */
#define OFF_B1 102400
#define OFF_B2 103168
#define SM_TOTAL 103936
#define NTHR 384
#define TILES_PER_CTA 8

__global__ void __launch_bounds__(NTHR, 2) k_cgemm(
    const float* __restrict__ b1r, const float* __restrict__ b1i,
    const float* __restrict__ b2r, const float* __restrict__ b2i) {
  extern __shared__ char smraw[];
  uint16_t* Asu = (uint16_t*)(smraw + OFF_AS);
  uint16_t* W1u = (uint16_t*)(smraw + OFF_W1);
  uint16_t* W2u = (uint16_t*)(smraw + OFF_W2);
  float* b1s = (float*)(smraw + OFF_B1);
  float* b2s = (float*)(smraw + OFF_B2);

  const int t = threadIdx.x, wid = t >> 5, lane = t & 31;
  const int b = blockIdx.y, nb = blockIdx.z;

  if (t < 192) {
    b1s[t] = (t < 96) ? b1r[nb * 96 + t] : b1i[nb * 96 + t - 96];
    b2s[t] = (t < 96) ? b2r[nb * 96 + t] : b2i[nb * 96 + t - 96];
  }
  const __nv_bfloat16* gw = g_Wexp + nb * 36864;
  for (int idx = t; idx < 2304; idx += NTHR) {
    const int n = idx / 24, c8 = (idx % 24) * 8;
    *(uint4*)(W1u + n * KP + c8) = *(const uint4*)(gw + n * 192 + c8);
    *(uint4*)(W2u + n * KP + c8) = *(const uint4*)(gw + 18432 + n * 192 + c8);
  }

  const long long chbase = ((long long)b * CC + nb * 96) * MODES;
  const int mwo = (wid & 1) * 32;           // 2 m-warps
  const int cb  = (wid >> 1) * 16;          // 6 channel groups of 16
  const int lrow = lane & 15, lcolh = (lane >> 4) * 8;
  const int frow = lane >> 2, fcol = 2 * (lane & 3);
  const int fmm = t & 63, fig = t >> 6;

  #pragma unroll 1
  for (int it = 0; it < TILES_PER_CTA; it++) {
    const int m0 = (blockIdx.x * TILES_PER_CTA + it) * 64;
    __syncthreads();
    // A tile: 16 coalesced LDG -> register transpose -> 4 conflict-free STS.128
    {
      const long long gb = chbase + (long long)(fig * 16) * MODES + m0 + fmm;
      uint32_t u[16];
      #pragma unroll
      for (int j = 0; j < 16; j++) u[j] = g_Xb[gb + (long long)j * MODES];
      uint32_t re[8], im[8];
      #pragma unroll
      for (int j = 0; j < 8; j++) {
        re[j] = (u[2 * j] & 0x0000ffffu) | (u[2 * j + 1] << 16);
        im[j] = (u[2 * j] >> 16)         | (u[2 * j + 1] & 0xffff0000u);
      }
      uint4* pre = (uint4*)(Asu + fmm * KP + fig * 16);
      pre[0] = make_uint4(re[0], re[1], re[2], re[3]);
      pre[1] = make_uint4(re[4], re[5], re[6], re[7]);
      uint4* pim = (uint4*)(Asu + fmm * KP + 96 + fig * 16);
      pim[0] = make_uint4(im[0], im[1], im[2], im[3]);
      pim[1] = make_uint4(im[4], im[5], im[6], im[7]);
    }
    __syncthreads();

    float acc[2][4][4];
    gemmPipe(Asu, W1u, mwo, cb, lrow, lcolh, acc);
    __syncthreads();   // all GEMM1 reads of As done

    // epilogue 1: bias + GELU -> H1 into Asu (nt<2: re cols, nt>=2: im cols)
    #pragma unroll
    for (int mt = 0; mt < 2; mt++)
      #pragma unroll
      for (int nt = 0; nt < 4; nt++) {
        const int col = ((nt < 2) ? cb + nt * 8 : 96 + cb + (nt - 2) * 8) + fcol;
        const float bl = b1s[col], bh = b1s[col + 1];
        const int r0 = mwo + mt * 16 + frow;
        __nv_bfloat162 p0, p1;
        p0.x = __float2bfloat16_rn(geluf(acc[mt][nt][0] + bl));
        p0.y = __float2bfloat16_rn(geluf(acc[mt][nt][1] + bh));
        p1.x = __float2bfloat16_rn(geluf(acc[mt][nt][2] + bl));
        p1.y = __float2bfloat16_rn(geluf(acc[mt][nt][3] + bh));
        *(__nv_bfloat162*)(Asu + r0 * KP + col)       = p0;
        *(__nv_bfloat162*)(Asu + (r0 + 8) * KP + col) = p1;
      }
    __syncthreads();   // H1 visible

    gemmPipe(Asu, W2u, mwo, cb, lrow, lcolh, acc);

    // epilogue 2: bias + softshrink, pack (re,im) -> single bf16x2 store
    #pragma unroll
    for (int mt = 0; mt < 2; mt++)
      #pragma unroll
      for (int nt = 0; nt < 2; nt++) {
        const int ch = cb + nt * 8 + fcol;
        const float brl = b2s[ch], brh = b2s[ch + 1];
        const float bil = b2s[ch + 96], bih = b2s[ch + 97];
        const int row = mwo + mt * 16 + frow;
        const long long base = chbase + (long long)ch * MODES + m0 + row;
        g_Yb[base] = packbf(make_float2(
            sshrink(acc[mt][nt][0] + brl), sshrink(acc[mt][nt + 2][0] + bil)));
        g_Yb[base + MODES] = packbf(make_float2(
            sshrink(acc[mt][nt][1] + brh), sshrink(acc[mt][nt + 2][1] + bih)));
        g_Yb[base + 8] = packbf(make_float2(
            sshrink(acc[mt][nt][2] + brl), sshrink(acc[mt][nt + 2][2] + bil)));
        g_Yb[base + MODES + 8] = packbf(make_float2(
            sshrink(acc[mt][nt][3] + brh), sshrink(acc[mt][nt + 2][3] + bih)));
      }
  }
}

// ---------------- Pass 5: inverse rFFT along D + residual ----------------
__global__ void __launch_bounds__(256) k_irfft_d(const float* __restrict__ x,
                                                 float* __restrict__ out) {
  __shared__ float sOut[8][32][33];
  const int t = threadIdx.x, warp = t >> 5, lane = t & 31;
  const int line0 = blockIdx.x * 256 + warp * 32;
  const int bc = line0 >> 10, h = (line0 >> 5) & 31;
  float2 v[32];
  const long long ib = (long long)bc * MODES + h * 32 + lane;
  #pragma unroll
  for (int k = 0; k < DR; k++) v[k] = unpackbf(g_Yb[ib + k * 1024]);
  #pragma unroll
  for (int k = DR; k < 32; k++) {
    const float2 z = v[32 - k];
    v[k] = make_float2(z.x, -z.y);
  }
  fft32<true>(v);
  #pragma unroll
  for (int d = 0; d < 32; d++) sOut[warp][lane][d] = v[d].x * S1;
  __syncwarp();
  const long long gb = (long long)line0 * 32;
  #pragma unroll
  for (int r = 0; r < 32; r++)
    out[gb + r * 32 + lane] = sOut[warp][r][lane] + x[gb + r * 32 + lane];
}

// ---------------- launch ----------------
extern "C" void kernel_launch(void* const* d_in, const int* in_sizes, int n_in,
                              void* d_out, int out_size) {
  const float* x   = (const float*)d_in[0];
  const float* w1r = (const float*)d_in[1];
  const float* w1i = (const float*)d_in[2];
  const float* w2r = (const float*)d_in[3];
  const float* w2i = (const float*)d_in[4];
  const float* b1r = (const float*)d_in[5];
  const float* b1i = (const float*)d_in[6];
  const float* b2r = (const float*)d_in[7];
  const float* b2i = (const float*)d_in[8];
  float* out = (float*)d_out;

  const int fftBytes = 8 * 1056 * (int)sizeof(uint32_t);   // 33792

  cudaFuncSetAttribute(k_fft_wh<false, false>,
                       cudaFuncAttributeMaxDynamicSharedMemorySize, fftBytes);
  cudaFuncSetAttribute(k_fft_wh<true, true>,
                       cudaFuncAttributeMaxDynamicSharedMemorySize, fftBytes);
  cudaFuncSetAttribute(k_cgemm,
                       cudaFuncAttributeMaxDynamicSharedMemorySize, SM_TOTAL);

  k_rfft_d<<<NLINES / 256, 256>>>(x, w1r, w1i, w2r, w2i);
  k_fft_wh<false, false><<<NPLANES / 8, 256, fftBytes>>>();
  dim3 g3(MODES / (64 * TILES_PER_CTA), 2, NBLK);
  k_cgemm<<<g3, NTHR, SM_TOTAL>>>(b1r, b1i, b2r, b2i);
  k_fft_wh<true, true><<<NPLANES / 8, 256, fftBytes>>>();
  k_irfft_d<<<NLINES / 256, 256>>>(x, out);
}